// round 16
// baseline (speedup 1.0000x reference)
#include <cuda_runtime.h>
#include <math.h>

#define NN 50000
#define NE 800000

__device__ float g_s1 [NN * 64];   // s @ W1_s / 8                  [n][c]
__device__ float g_v1 [NN * 96];   // v . W1_v / sqrt(32)           [n][i*32+u]
__device__ float g_ags[NN * 64];   // scalar aggregate              [n][c*2+h]
__device__ float g_agv[NN * 128];  // vector aggregate              [n][u*4+i] (i=3 pad)
__device__ float g_w  [NE * 192];  // edge MLP output w / sqrt(8)   [e][c]

typedef unsigned long long u64;

__device__ __forceinline__ float sigmoidf_(float x) { return 1.0f / (1.0f + __expf(-x)); }
__device__ __forceinline__ float siluf_(float x)    { return x / (1.0f + __expf(-x)); }

__device__ __forceinline__ u64 pk2(float x) {
    u64 r; asm("mov.b64 %0, {%1, %1};" : "=l"(r) : "f"(x)); return r;
}
__device__ __forceinline__ float2 up2(u64 v) {
    float2 r; asm("mov.b64 {%0, %1}, %2;" : "=f"(r.x), "=f"(r.y) : "l"(v)); return r;
}
__device__ __forceinline__ void ff2(u64& d, u64 a, u64 b) {
    asm("fma.rn.f32x2 %0, %1, %2, %0;" : "+l"(d) : "l"(a), "l"(b));
}
__device__ __forceinline__ void redf(float* p, float v) {
    asm volatile("red.global.add.f32 [%0], %1;" :: "l"(p), "f"(v) : "memory");
}
__device__ __forceinline__ void redv2(float* p, float a, float b) {
    asm volatile("red.global.add.v2.f32 [%0], {%1,%2};"
                 :: "l"(p), "f"(a), "f"(b) : "memory");
}
__device__ __forceinline__ float ldcs(const float* p) { return __ldcs(p); }
__device__ __forceinline__ float4 ldcs4(const float4* p) { return __ldcs(p); }
__device__ __forceinline__ float ldcg(const float* p) { return __ldcg(p); }

// ---------------------------------------------------------------------------
// Kernel 1: node pre-transform (one warp per node) + zero aggregates
// ---------------------------------------------------------------------------
__global__ void __launch_bounds__(256) k_node_pre(
    const float* __restrict__ feats,
    const float* __restrict__ W1s,
    const float* __restrict__ W1v)
{
    __shared__ float sW1s[64 * 64];
    __shared__ float sW1v[32 * 32];
    __shared__ float stage[8][160];

    int tid = threadIdx.x;
    {
        int gidx = blockIdx.x * 256 + tid;
        float4 z = make_float4(0.f, 0.f, 0.f, 0.f);
        if (gidx < NN * 16) ((float4*)g_ags)[gidx] = z;   // 800k float4
        ((float4*)g_agv)[gidx] = z;                       // 1.6M float4 exact
    }
    for (int i = tid; i < 4096; i += 256) sW1s[i] = W1s[i];
    for (int i = tid; i < 1024; i += 256) sW1v[i] = W1v[i];
    __syncthreads();

    int warp = tid >> 5, lane = tid & 31;
    int n = blockIdx.x * 8 + warp;
    if (n >= NN) return;

    #pragma unroll
    for (int j = 0; j < 5; j++)
        stage[warp][lane * 5 + j] = feats[n * 160 + lane * 5 + j];
    __syncwarp();

    float a0 = 0.f, a1 = 0.f;
    #pragma unroll 8
    for (int u = 0; u < 64; u++) {
        float su = stage[warp][u];
        a0 += su * sW1s[u * 64 + lane];
        a1 += su * sW1s[u * 64 + 32 + lane];
    }
    g_s1[n * 64 + lane]      = a0 * 0.125f;
    g_s1[n * 64 + 32 + lane] = a1 * 0.125f;

    float b0 = 0.f, b1 = 0.f, b2 = 0.f;
    #pragma unroll 8
    for (int u = 0; u < 32; u++) {
        float wv = sW1v[u * 32 + lane];
        const float* vp = &stage[warp][64 + u * 3];
        b0 += vp[0] * wv; b1 += vp[1] * wv; b2 += vp[2] * wv;
    }
    const float sv = 0.17677669529663687f;
    g_v1[n * 96 +      lane] = b0 * sv;
    g_v1[n * 96 + 32 + lane] = b1 * sv;
    g_v1[n * 96 + 64 + lane] = b2 * sv;
}

// ---------------------------------------------------------------------------
// Kernel 1b: edge MLP precompute. mw1 columns held in REGISTERS (48/thread,
// loaded once) — removes 48 coalesced LDS per edge from the L1-bound branch.
// ---------------------------------------------------------------------------
__global__ void __launch_bounds__(256) k_mlp(
    const float* __restrict__ emb,  // (E,8)
    const float* __restrict__ mw0,  // (8,8)
    const float* __restrict__ mw1)  // (8,192)
{
    __shared__ float sMw0[64];
    int tid = threadIdx.x;
    for (int i = tid; i < 64; i += 256) sMw0[i] = mw0[i];
    __syncthreads();

    int warp = tid >> 5, lane = tid & 31;

    // per-thread weight slice: rw[q][c] = mw1[q][c*32 + lane]
    float rw[8][6];
    #pragma unroll
    for (int q = 0; q < 8; q++)
        #pragma unroll
        for (int c = 0; c < 6; c++)
            rw[q][c] = mw1[q * 192 + c * 32 + lane];

    const float is8 = 0.35355339059327373f;  // 1/sqrt(8)
    int e0 = (blockIdx.x * 8 + warp) * 4;    // 25000 blocks * 32 edges = NE

    #pragma unroll
    for (int j = 0; j < 4; j++) {
        int e = e0 + j;
        float4 em0 = ldcs4((const float4*)emb + e * 2 + 0);
        float4 em1 = ldcs4((const float4*)emb + e * 2 + 1);
        float em[8] = {em0.x, em0.y, em0.z, em0.w, em1.x, em1.y, em1.z, em1.w};
        float h[8];
        #pragma unroll
        for (int q = 0; q < 8; q++) {
            float t = 0.f;
            #pragma unroll
            for (int k = 0; k < 8; k++) t += em[k] * sMw0[k * 8 + q];
            h[q] = siluf_(t * is8);
        }
        float wa = 0.f, wb = 0.f, wc = 0.f, wd = 0.f, we = 0.f, wf = 0.f;
        #pragma unroll
        for (int q = 0; q < 8; q++) {
            float hq = h[q];
            wa += hq * rw[q][0]; wb += hq * rw[q][1];
            wc += hq * rw[q][2]; wd += hq * rw[q][3];
            we += hq * rw[q][4]; wf += hq * rw[q][5];
        }
        float* wp = &g_w[(long long)e * 192];
        wp[lane]       = wa * is8;  wp[32 + lane]  = wb * is8;
        wp[64 + lane]  = wc * is8;  wp[96 + lane]  = wd * is8;
        wp[128 + lane] = we * is8;  wp[160 + lane] = wf * is8;
    }
}

// ---------------------------------------------------------------------------
// Kernel 2: edge kernel. 4 warps/block, 8 edges/warp as 2 float4 quads,
// 5 blocks/SM. Weights from L1; gathers ld.cg; scatter via red.v2 pairs.
// ---------------------------------------------------------------------------
__global__ void __launch_bounds__(128, 5) k_edge(
    const float* __restrict__ ea,   // edge_attrs  (E,4)
    const float* __restrict__ W2s,  // (96,96)  - via L1
    const float* __restrict__ W2v,  // (96,32)  - via L1
    const int*   __restrict__ ei)   // (2,E)
{
    __shared__ float sStg[4][2048];  // per-warp: A 768 | B 512 | C 768 floats

    int warp = threadIdx.x >> 5, lane = threadIdx.x & 31;
    float* stg = sStg[warp];
    float4* A4 = (float4*)stg;                    // [q*96 + c]
    float4* B4 = (float4*)(stg + 768);            // [q*64 + c]
    float4* C4 = (float4*)(stg + 1280);           // [q*96 + c]
    const ulonglong2* A2 = (const ulonglong2*)A4;
    const ulonglong2* B2 = (const ulonglong2*)B4;
    const ulonglong2* C2 = (const ulonglong2*)C4;

    const float is96 = 0.10206207261596575f;  // 1/sqrt(96)
    const float is3  = 0.57735026918962576f;  // 1/sqrt(3)

    int e0 = (blockIdx.x * 4 + warp) * 8;     // 25000*32 = NE exact, no tail

    int dsts[8];
    #pragma unroll
    for (int j = 0; j < 8; j++) dsts[j] = __ldcs(&ei[NE + e0 + j]);

    // ---- phase 1: build quad-packed staged messages ----
    #pragma unroll
    for (int q = 0; q < 2; q++) {
        float bA0[4], bA1[4], bA2[4], bB0[4], bB1[4], bC0[4], bC1[4], bC2[4];
        #pragma unroll
        for (int h = 0; h < 4; h++) {
            int e = e0 + q * 4 + h;
            int src = __ldcs(&ei[e]);

            float se0 = ldcg(&g_s1[src * 64 + lane]);
            float se1 = ldcg(&g_s1[src * 64 + 32 + lane]);
            float vx  = ldcg(&g_v1[src * 96 +      lane]);
            float vy  = ldcg(&g_v1[src * 96 + 32 + lane]);
            float vz  = ldcg(&g_v1[src * 96 + 64 + lane]);

            const float* wp = &g_w[(long long)e * 192];
            float wa = ldcs(&wp[lane]);
            float wb = ldcs(&wp[32 + lane]);
            float wc = ldcs(&wp[64 + lane]);
            float wd = ldcs(&wp[96 + lane]);
            float we = ldcs(&wp[128 + lane]);
            float wf = ldcs(&wp[160 + lane]);

            float4 yv = ldcs4((const float4*)ea + e);
            float Y0 = yv.x, yx = yv.y, yy = yv.z, yz = yv.w;

            bA0[h] = wa * se0 * Y0;
            bA1[h] = wb * se1 * Y0;
            bA2[h] = wf * (vx * yx + vy * yy + vz * yz) * is3;
            bB0[h] = wc * se0;
            bB1[h] = wd * se1;
            float q0 = we * Y0;
            bC0[h] = q0 * vx;
            bC1[h] = q0 * vy;
            bC2[h] = q0 * vz;
        }
        A4[q * 96 +      lane] = make_float4(bA0[0], bA0[1], bA0[2], bA0[3]);
        A4[q * 96 + 32 + lane] = make_float4(bA1[0], bA1[1], bA1[2], bA1[3]);
        A4[q * 96 + 64 + lane] = make_float4(bA2[0], bA2[1], bA2[2], bA2[3]);
        B4[q * 64 +      lane] = make_float4(bB0[0], bB0[1], bB0[2], bB0[3]);
        B4[q * 64 + 32 + lane] = make_float4(bB1[0], bB1[1], bB1[2], bB1[3]);
        C4[q * 96 +      lane] = make_float4(bC0[0], bC0[1], bC0[2], bC0[3]);
        C4[q * 96 + 32 + lane] = make_float4(bC1[0], bC1[1], bC1[2], bC1[3]);
        C4[q * 96 + 64 + lane] = make_float4(bC2[0], bC2[1], bC2[2], bC2[3]);
    }
    __syncwarp();

    float gate[8];

    // ---- phase 2a: scalar (ms) matvec; 12 u64 accumulators live ----
    {
        u64 aS0[4], aS1[4], aS2[4];
        #pragma unroll
        for (int p = 0; p < 4; p++) { aS0[p] = aS1[p] = aS2[p] = 0ULL; }

        #pragma unroll 4
        for (int u = 0; u < 96; u++) {
            u64 W0 = pk2(W2s[u * 96 + lane]);
            u64 W1 = pk2(W2s[u * 96 + 32 + lane]);
            u64 W2 = pk2(W2s[u * 96 + 64 + lane]);
            #pragma unroll
            for (int q = 0; q < 2; q++) {
                ulonglong2 a = A2[q * 96 + u];        // broadcast LDS.128
                ff2(aS0[2*q], a.x, W0); ff2(aS0[2*q+1], a.y, W0);
                ff2(aS1[2*q], a.x, W1); ff2(aS1[2*q+1], a.y, W1);
                ff2(aS2[2*q], a.x, W2); ff2(aS2[2*q+1], a.y, W2);
            }
        }

        // ---- phase 3a: gate + paired scalar-aggregate scatter ----
        #pragma unroll
        for (int pr = 0; pr < 4; pr++) {
            float2 m0 = up2(aS0[pr]), m1 = up2(aS1[pr]), m2 = up2(aS2[pr]);
            #pragma unroll
            for (int h = 0; h < 2; h++) {
                int j = 4 * (pr >> 1) + (pr & 1) * 2 + h;
                int dst = dsts[j];
                float M0 = (h ? m0.y : m0.x) * is96;
                float M1 = (h ? m1.y : m1.x) * is96;
                float M2 = (h ? m2.y : m2.x) * is96;
                gate[j] = sigmoidf_(M2) * 0.25f;
                redv2(&g_ags[dst * 64 + lane * 2],
                      siluf_(M0) * 0.25f, siluf_(M1) * 0.25f);
            }
        }
    }

    // ---- phase 2b: vector (mv) matvecs; 16 u64 accumulators live ----
    {
        u64 aB[4], aCx[4], aCy[4], aCz[4];
        #pragma unroll
        for (int p = 0; p < 4; p++) { aB[p] = aCx[p] = aCy[p] = aCz[p] = 0ULL; }

        #pragma unroll 4
        for (int u = 0; u < 64; u++) {
            u64 W = pk2(W2v[u * 32 + lane]);
            #pragma unroll
            for (int q = 0; q < 2; q++) {
                ulonglong2 b = B2[q * 64 + u];
                ff2(aB[2*q], b.x, W); ff2(aB[2*q+1], b.y, W);
            }
        }
        #pragma unroll 4
        for (int u = 0; u < 32; u++) {
            u64 W = pk2(W2v[(64 + u) * 32 + lane]);
            #pragma unroll
            for (int q = 0; q < 2; q++) {
                ulonglong2 cx = C2[q * 96 +      u];
                ulonglong2 cy = C2[q * 96 + 32 + u];
                ulonglong2 cz = C2[q * 96 + 64 + u];
                ff2(aCx[2*q], cx.x, W); ff2(aCx[2*q+1], cx.y, W);
                ff2(aCy[2*q], cy.x, W); ff2(aCy[2*q+1], cy.y, W);
                ff2(aCz[2*q], cz.x, W); ff2(aCz[2*q+1], cz.y, W);
            }
        }

        // ---- phase 3b: paired vector-aggregate scatter ----
        #pragma unroll
        for (int pr = 0; pr < 4; pr++) {
            float2 t1 = up2(aB[pr]);
            float2 cx = up2(aCx[pr]), cy = up2(aCy[pr]), cz = up2(aCz[pr]);
            #pragma unroll
            for (int h = 0; h < 2; h++) {
                int j = 4 * (pr >> 1) + (pr & 1) * 2 + h;
                int e = e0 + j;
                int dst = dsts[j];
                float4 yv = ldcs4((const float4*)ea + e);
                float T1 = (h ? t1.y : t1.x) * is96;
                float Cx = (h ? cx.y : cx.x) * is96;
                float Cy = (h ? cy.y : cy.x) * is96;
                float Cz = (h ? cz.y : cz.x) * is96;
                float g = gate[j];
                float* vp = &g_agv[dst * 128 + lane * 4];
                redv2(vp, (T1 * yv.y + Cx) * g, (T1 * yv.z + Cy) * g);
                redf(vp + 2, (T1 * yv.w + Cz) * g);
            }
        }
    }
}

// ---------------------------------------------------------------------------
// Kernel 3: node post. 8 nodes/block, 192 threads; [k][p] pair layout; ts/tv
// halves run concurrently; f32x2 node-pair packing. Paired aggregate layouts.
// ---------------------------------------------------------------------------
__global__ void __launch_bounds__(192, 2) k_node_post(
    const float* __restrict__ feats,
    const float* __restrict__ attrs,
    const float* __restrict__ Us,   // (64,16)
    const float* __restrict__ Uv,   // (32,16)
    const float* __restrict__ W3s,  // (64,96)
    const float* __restrict__ W3v,  // (32,32)
    const float* __restrict__ SCs,  // (64,16,96)
    const float* __restrict__ SCv,  // (32,16,32)
    float* __restrict__ out)
{
    extern __shared__ float sm[];
    float* cS2    = sm;          // 8192:  [k*8 + p*2 + h]
    float* cV2    = sm + 8192;   // 12288: [(iv*512+k)*8 + p*2 + h]
    float* us2    = sm + 20480;  // 512
    float* uv2    = sm + 20992;  // 768
    float* attr_s = sm + 21760;  // 128
    float* sS     = sm + 21888;  // 512
    float* sV     = sm + 22400;  // 768
    float* gate_s = sm + 23168;  // 256

    int tid = threadIdx.x;
    int nbase = blockIdx.x * 8;

    for (int i = tid; i < 8 * 160; i += 192) {
        int t = i / 160, c = i % 160;
        float v = feats[(nbase + t) * 160 + c];
        if (c < 64) sS[t * 64 + c] = v; else sV[t * 96 + (c - 64)] = v;
    }
    for (int i = tid; i < 128; i += 192) attr_s[i] = attrs[nbase * 16 + i];
    __syncthreads();

    for (int i = tid; i < 8192; i += 192) {
        int h = i & 1, p = (i >> 1) & 3, k = i >> 3;
        int t = 2 * p + h, u = k >> 4, v = k & 15;
        cS2[i] = sS[t * 64 + u] * attr_s[t * 16 + v];
    }
    for (int i = tid; i < 12288; i += 192) {
        int h = i & 1, p = (i >> 1) & 3, kk = i >> 3;
        int iv = kk >> 9, k = kk & 511;
        int t = 2 * p + h, u = k >> 4, v = k & 15;
        cV2[i] = sV[t * 96 + u * 3 + iv] * attr_s[t * 16 + v];
    }
    for (int i = tid; i < 512; i += 192) {
        int h = i & 1, p = (i >> 1) & 3, u = i >> 3;
        int t = 2 * p + h;
        float d = 0.f;
        #pragma unroll
        for (int v = 0; v < 16; v++) d += attr_s[t * 16 + v] * Us[u * 16 + v];
        us2[i] = g_ags[(nbase + t) * 64 + ((u & 31) * 2) + (u >> 5)] * d * 0.25f;
    }
    for (int i = tid; i < 768; i += 192) {
        int h = i & 1, p = (i >> 1) & 3, idx = i >> 3;
        int iv = idx >> 5, u = idx & 31;
        int t = 2 * p + h;
        float d = 0.f;
        #pragma unroll
        for (int v = 0; v < 16; v++) d += attr_s[t * 16 + v] * Uv[u * 16 + v];
        uv2[i] = g_agv[(nbase + t) * 128 + u * 4 + iv] * d * 0.25f;
    }
    __syncthreads();

    int half = tid / 96;
    int r    = tid % 96;

    if (half == 0) {
        int w = r;
        u64 a1[4] = {0,0,0,0}, a2[4] = {0,0,0,0};
        const ulonglong2* us4 = (const ulonglong2*)us2;
        const ulonglong2* cs4 = (const ulonglong2*)cS2;
        #pragma unroll 8
        for (int u = 0; u < 64; u++) {
            u64 W = pk2(W3s[u * 96 + w]);
            ulonglong2 x0 = us4[u * 2 + 0], x1 = us4[u * 2 + 1];
            ff2(a1[0], x0.x, W); ff2(a1[1], x0.y, W);
            ff2(a1[2], x1.x, W); ff2(a1[3], x1.y, W);
        }
        #pragma unroll 8
        for (int k = 0; k < 1024; k++) {
            u64 W = pk2(SCs[k * 96 + w]);
            ulonglong2 x0 = cs4[k * 2 + 0], x1 = cs4[k * 2 + 1];
            ff2(a2[0], x0.x, W); ff2(a2[1], x0.y, W);
            ff2(a2[2], x1.x, W); ff2(a2[3], x1.y, W);
        }
        float ts[8];
        #pragma unroll
        for (int p = 0; p < 4; p++) {
            float2 x1 = up2(a1[p]), x2 = up2(a2[p]);
            ts[2 * p]     = x1.x * 0.125f + x2.x * 0.03125f;
            ts[2 * p + 1] = x1.y * 0.125f + x2.y * 0.03125f;
        }
        if (w < 64) {
            #pragma unroll
            for (int t = 0; t < 8; t++)
                out[(nbase + t) * 160 + w] = siluf_(ts[t]);
        } else {
            #pragma unroll
            for (int t = 0; t < 8; t++)
                gate_s[t * 32 + (w - 64)] = sigmoidf_(ts[t]);
        }
        __syncthreads();
    } else {
        int wv = r & 31, iv = r >> 5;
        u64 b1[4] = {0,0,0,0}, b2[4] = {0,0,0,0};
        const ulonglong2* uv4 = (const ulonglong2*)uv2;
        const ulonglong2* cv4 = (const ulonglong2*)cV2;
        #pragma unroll 8
        for (int u = 0; u < 32; u++) {
            u64 W = pk2(W3v[u * 32 + wv]);
            ulonglong2 x0 = uv4[(iv * 32 + u) * 2 + 0];
            ulonglong2 x1 = uv4[(iv * 32 + u) * 2 + 1];
            ff2(b1[0], x0.x, W); ff2(b1[1], x0.y, W);
            ff2(b1[2], x1.x, W); ff2(b1[3], x1.y, W);
        }
        #pragma unroll 8
        for (int k = 0; k < 512; k++) {
            u64 W = pk2(SCv[k * 32 + wv]);
            ulonglong2 x0 = cv4[(iv * 512 + k) * 2 + 0];
            ulonglong2 x1 = cv4[(iv * 512 + k) * 2 + 1];
            ff2(b2[0], x0.x, W); ff2(b2[1], x0.y, W);
            ff2(b2[2], x1.x, W); ff2(b2[3], x1.y, W);
        }
        __syncthreads();

        const float isv  = 0.17677669529663687f;  // 1/sqrt(32)
        const float isvn = 0.044194173824159220f; // 1/sqrt(512)
        #pragma unroll
        for (int p = 0; p < 4; p++) {
            float2 x1 = up2(b1[p]), x2 = up2(b2[p]);
            float tv0 = x1.x * isv + x2.x * isvn;
            float tv1 = x1.y * isv + x2.y * isvn;
            out[(nbase + 2 * p)     * 160 + 64 + wv * 3 + iv] = tv0 * gate_s[(2 * p)     * 32 + wv];
            out[(nbase + 2 * p + 1) * 160 + 64 + wv * 3 + iv] = tv1 * gate_s[(2 * p + 1) * 32 + wv];
        }
    }
}

// ---------------------------------------------------------------------------
extern "C" void kernel_launch(void* const* d_in, const int* in_sizes, int n_in,
                              void* d_out, int out_size)
{
    const float* node_feats = (const float*)d_in[0];
    const float* node_attrs = (const float*)d_in[1];
    const float* edge_attrs = (const float*)d_in[2];
    const float* edge_emb   = (const float*)d_in[3];
    const float* W1s        = (const float*)d_in[4];
    const float* W1v        = (const float*)d_in[5];
    const float* mw0        = (const float*)d_in[6];
    const float* mw1        = (const float*)d_in[7];
    const float* W2s        = (const float*)d_in[8];
    const float* W2v        = (const float*)d_in[9];
    const float* Us         = (const float*)d_in[10];
    const float* Uv         = (const float*)d_in[11];
    const float* W3s        = (const float*)d_in[12];
    const float* W3v        = (const float*)d_in[13];
    const float* SCs        = (const float*)d_in[14];
    const float* SCv        = (const float*)d_in[15];
    const int*   ei         = (const int*)  d_in[16];
    float* out = (float*)d_out;

    k_node_pre<<<6250, 256>>>(node_feats, W1s, W1v);

    // 25000 blocks * 8 warps * 4 edges = 800000 exactly
    k_mlp<<<25000, 256>>>(edge_emb, mw0, mw1);

    // 25000 blocks * 4 warps * 8 edges = 800000 exactly
    k_edge<<<25000, 128>>>(edge_attrs, W2s, W2v, ei);

    cudaFuncSetAttribute(k_node_post, cudaFuncAttributeMaxDynamicSharedMemorySize, 94208);
    k_node_post<<<6250, 192, 93696>>>(node_feats, node_attrs, Us, Uv, W3s, W3v,
                                      SCs, SCv, out);
}

// round 17
// speedup vs baseline: 1.1348x; 1.1348x over previous
#include <cuda_runtime.h>
#include <math.h>

#define NN 50000
#define NE 800000

__device__ float g_s1 [NN * 64];   // s @ W1_s / 8                  [n][c]
__device__ float g_v1 [NN * 96];   // v . W1_v / sqrt(32)           [n][i*32+u]
__device__ float g_ags[NN * 64];   // scalar aggregate              [n][c*2+h]
__device__ float g_agv[NN * 128];  // vector aggregate              [n][u*4+i] (i=3 pad)
__device__ float g_w  [NE * 192];  // edge MLP output w / sqrt(8)   [e][c]

typedef unsigned long long u64;

__device__ __forceinline__ float sigmoidf_(float x) { return 1.0f / (1.0f + __expf(-x)); }
__device__ __forceinline__ float siluf_(float x)    { return x / (1.0f + __expf(-x)); }

__device__ __forceinline__ u64 pk2(float x) {
    u64 r; asm("mov.b64 %0, {%1, %1};" : "=l"(r) : "f"(x)); return r;
}
__device__ __forceinline__ float2 up2(u64 v) {
    float2 r; asm("mov.b64 {%0, %1}, %2;" : "=f"(r.x), "=f"(r.y) : "l"(v)); return r;
}
__device__ __forceinline__ void ff2(u64& d, u64 a, u64 b) {
    asm("fma.rn.f32x2 %0, %1, %2, %0;" : "+l"(d) : "l"(a), "l"(b));
}
__device__ __forceinline__ void redf(float* p, float v) {
    asm volatile("red.global.add.f32 [%0], %1;" :: "l"(p), "f"(v) : "memory");
}
__device__ __forceinline__ void redv2(float* p, float a, float b) {
    asm volatile("red.global.add.v2.f32 [%0], {%1,%2};"
                 :: "l"(p), "f"(a), "f"(b) : "memory");
}
__device__ __forceinline__ float ldcs(const float* p) { return __ldcs(p); }
__device__ __forceinline__ float4 ldcs4(const float4* p) { return __ldcs(p); }
__device__ __forceinline__ float ldcg(const float* p) { return __ldcg(p); }

// ---------------------------------------------------------------------------
// Kernel 1: node pre-transform (one warp per node) + zero aggregates
// ---------------------------------------------------------------------------
__global__ void __launch_bounds__(256) k_node_pre(
    const float* __restrict__ feats,
    const float* __restrict__ W1s,
    const float* __restrict__ W1v)
{
    __shared__ float sW1s[64 * 64];
    __shared__ float sW1v[32 * 32];
    __shared__ float stage[8][160];

    int tid = threadIdx.x;
    {
        int gidx = blockIdx.x * 256 + tid;
        float4 z = make_float4(0.f, 0.f, 0.f, 0.f);
        if (gidx < NN * 16) ((float4*)g_ags)[gidx] = z;   // 800k float4
        ((float4*)g_agv)[gidx] = z;                       // 1.6M float4 exact
    }
    for (int i = tid; i < 4096; i += 256) sW1s[i] = W1s[i];
    for (int i = tid; i < 1024; i += 256) sW1v[i] = W1v[i];
    __syncthreads();

    int warp = tid >> 5, lane = tid & 31;
    int n = blockIdx.x * 8 + warp;
    if (n >= NN) return;

    #pragma unroll
    for (int j = 0; j < 5; j++)
        stage[warp][lane * 5 + j] = feats[n * 160 + lane * 5 + j];
    __syncwarp();

    float a0 = 0.f, a1 = 0.f;
    #pragma unroll 8
    for (int u = 0; u < 64; u++) {
        float su = stage[warp][u];
        a0 += su * sW1s[u * 64 + lane];
        a1 += su * sW1s[u * 64 + 32 + lane];
    }
    g_s1[n * 64 + lane]      = a0 * 0.125f;
    g_s1[n * 64 + 32 + lane] = a1 * 0.125f;

    float b0 = 0.f, b1 = 0.f, b2 = 0.f;
    #pragma unroll 8
    for (int u = 0; u < 32; u++) {
        float wv = sW1v[u * 32 + lane];
        const float* vp = &stage[warp][64 + u * 3];
        b0 += vp[0] * wv; b1 += vp[1] * wv; b2 += vp[2] * wv;
    }
    const float sv = 0.17677669529663687f;
    g_v1[n * 96 +      lane] = b0 * sv;
    g_v1[n * 96 + 32 + lane] = b1 * sv;
    g_v1[n * 96 + 64 + lane] = b2 * sv;
}

// ---------------------------------------------------------------------------
// Kernel 1b: edge MLP. Phase A: 256 threads = 32 edges x 8 h-components,
// each h computed ONCE (not per-lane). Phase B: warp per 4 edges, second
// layer from register-resident mw1 slice, h via broadcast LDS.
// ---------------------------------------------------------------------------
__global__ void __launch_bounds__(256) k_mlp(
    const float* __restrict__ emb,  // (E,8)
    const float* __restrict__ mw0,  // (8,8)
    const float* __restrict__ mw1)  // (8,192)
{
    __shared__ float sMw0[64];
    __shared__ float sH[256];        // [eLocal*8 + q]
    int tid = threadIdx.x;
    for (int i = tid; i < 64; i += 256) sMw0[i] = mw0[i];

    int warp = tid >> 5, lane = tid & 31;

    // per-thread second-layer weight slice: rw[q][c] = mw1[q][c*32 + lane]
    float rw[8][6];
    #pragma unroll
    for (int q = 0; q < 8; q++)
        #pragma unroll
        for (int c = 0; c < 6; c++)
            rw[q][c] = mw1[q * 192 + c * 32 + lane];
    __syncthreads();

    const float is8 = 0.35355339059327373f;  // 1/sqrt(8)
    int eBase = blockIdx.x * 32;             // 25000 blocks * 32 edges = NE

    // ---- phase A: one thread per (edge, q) ----
    {
        int eLocal = tid >> 3;
        int q = tid & 7;
        int e = eBase + eLocal;
        float4 em0 = ldcs4((const float4*)emb + e * 2 + 0);
        float4 em1 = ldcs4((const float4*)emb + e * 2 + 1);
        float em[8] = {em0.x, em0.y, em0.z, em0.w, em1.x, em1.y, em1.z, em1.w};
        float t = 0.f;
        #pragma unroll
        for (int k = 0; k < 8; k++) t += em[k] * sMw0[k * 8 + q];
        sH[eLocal * 8 + q] = siluf_(t * is8);
    }
    __syncthreads();

    // ---- phase B: warp handles 4 edges; h via broadcast LDS ----
    #pragma unroll
    for (int j = 0; j < 4; j++) {
        int eLocal = warp * 4 + j;
        int e = eBase + eLocal;
        float wa = 0.f, wb = 0.f, wc = 0.f, wd = 0.f, we = 0.f, wf = 0.f;
        #pragma unroll
        for (int q = 0; q < 8; q++) {
            float hq = sH[eLocal * 8 + q];
            wa += hq * rw[q][0]; wb += hq * rw[q][1];
            wc += hq * rw[q][2]; wd += hq * rw[q][3];
            we += hq * rw[q][4]; wf += hq * rw[q][5];
        }
        float* wp = &g_w[(long long)e * 192];
        wp[lane]       = wa * is8;  wp[32 + lane]  = wb * is8;
        wp[64 + lane]  = wc * is8;  wp[96 + lane]  = wd * is8;
        wp[128 + lane] = we * is8;  wp[160 + lane] = wf * is8;
    }
}

// ---------------------------------------------------------------------------
// Kernel 2: edge kernel. 4 warps/block, 8 edges/warp as 2 float4 quads,
// 5 blocks/SM. Weights from L1; gathers ld.cg; scatter via red.v2 pairs.
// ---------------------------------------------------------------------------
__global__ void __launch_bounds__(128, 5) k_edge(
    const float* __restrict__ ea,   // edge_attrs  (E,4)
    const float* __restrict__ W2s,  // (96,96)  - via L1
    const float* __restrict__ W2v,  // (96,32)  - via L1
    const int*   __restrict__ ei)   // (2,E)
{
    __shared__ float sStg[4][2048];  // per-warp: A 768 | B 512 | C 768 floats

    int warp = threadIdx.x >> 5, lane = threadIdx.x & 31;
    float* stg = sStg[warp];
    float4* A4 = (float4*)stg;                    // [q*96 + c]
    float4* B4 = (float4*)(stg + 768);            // [q*64 + c]
    float4* C4 = (float4*)(stg + 1280);           // [q*96 + c]
    const ulonglong2* A2 = (const ulonglong2*)A4;
    const ulonglong2* B2 = (const ulonglong2*)B4;
    const ulonglong2* C2 = (const ulonglong2*)C4;

    const float is96 = 0.10206207261596575f;  // 1/sqrt(96)
    const float is3  = 0.57735026918962576f;  // 1/sqrt(3)

    int e0 = (blockIdx.x * 4 + warp) * 8;     // 25000*32 = NE exact, no tail

    int dsts[8];
    #pragma unroll
    for (int j = 0; j < 8; j++) dsts[j] = __ldcs(&ei[NE + e0 + j]);

    // ---- phase 1: build quad-packed staged messages ----
    #pragma unroll
    for (int q = 0; q < 2; q++) {
        float bA0[4], bA1[4], bA2[4], bB0[4], bB1[4], bC0[4], bC1[4], bC2[4];
        #pragma unroll
        for (int h = 0; h < 4; h++) {
            int e = e0 + q * 4 + h;
            int src = __ldcs(&ei[e]);

            float se0 = ldcg(&g_s1[src * 64 + lane]);
            float se1 = ldcg(&g_s1[src * 64 + 32 + lane]);
            float vx  = ldcg(&g_v1[src * 96 +      lane]);
            float vy  = ldcg(&g_v1[src * 96 + 32 + lane]);
            float vz  = ldcg(&g_v1[src * 96 + 64 + lane]);

            const float* wp = &g_w[(long long)e * 192];
            float wa = ldcs(&wp[lane]);
            float wb = ldcs(&wp[32 + lane]);
            float wc = ldcs(&wp[64 + lane]);
            float wd = ldcs(&wp[96 + lane]);
            float we = ldcs(&wp[128 + lane]);
            float wf = ldcs(&wp[160 + lane]);

            float4 yv = ldcs4((const float4*)ea + e);
            float Y0 = yv.x, yx = yv.y, yy = yv.z, yz = yv.w;

            bA0[h] = wa * se0 * Y0;
            bA1[h] = wb * se1 * Y0;
            bA2[h] = wf * (vx * yx + vy * yy + vz * yz) * is3;
            bB0[h] = wc * se0;
            bB1[h] = wd * se1;
            float q0 = we * Y0;
            bC0[h] = q0 * vx;
            bC1[h] = q0 * vy;
            bC2[h] = q0 * vz;
        }
        A4[q * 96 +      lane] = make_float4(bA0[0], bA0[1], bA0[2], bA0[3]);
        A4[q * 96 + 32 + lane] = make_float4(bA1[0], bA1[1], bA1[2], bA1[3]);
        A4[q * 96 + 64 + lane] = make_float4(bA2[0], bA2[1], bA2[2], bA2[3]);
        B4[q * 64 +      lane] = make_float4(bB0[0], bB0[1], bB0[2], bB0[3]);
        B4[q * 64 + 32 + lane] = make_float4(bB1[0], bB1[1], bB1[2], bB1[3]);
        C4[q * 96 +      lane] = make_float4(bC0[0], bC0[1], bC0[2], bC0[3]);
        C4[q * 96 + 32 + lane] = make_float4(bC1[0], bC1[1], bC1[2], bC1[3]);
        C4[q * 96 + 64 + lane] = make_float4(bC2[0], bC2[1], bC2[2], bC2[3]);
    }
    __syncwarp();

    float gate[8];

    // ---- phase 2a: scalar (ms) matvec; 12 u64 accumulators live ----
    {
        u64 aS0[4], aS1[4], aS2[4];
        #pragma unroll
        for (int p = 0; p < 4; p++) { aS0[p] = aS1[p] = aS2[p] = 0ULL; }

        #pragma unroll 4
        for (int u = 0; u < 96; u++) {
            u64 W0 = pk2(W2s[u * 96 + lane]);
            u64 W1 = pk2(W2s[u * 96 + 32 + lane]);
            u64 W2 = pk2(W2s[u * 96 + 64 + lane]);
            #pragma unroll
            for (int q = 0; q < 2; q++) {
                ulonglong2 a = A2[q * 96 + u];        // broadcast LDS.128
                ff2(aS0[2*q], a.x, W0); ff2(aS0[2*q+1], a.y, W0);
                ff2(aS1[2*q], a.x, W1); ff2(aS1[2*q+1], a.y, W1);
                ff2(aS2[2*q], a.x, W2); ff2(aS2[2*q+1], a.y, W2);
            }
        }

        // ---- phase 3a: gate + paired scalar-aggregate scatter ----
        #pragma unroll
        for (int pr = 0; pr < 4; pr++) {
            float2 m0 = up2(aS0[pr]), m1 = up2(aS1[pr]), m2 = up2(aS2[pr]);
            #pragma unroll
            for (int h = 0; h < 2; h++) {
                int j = 4 * (pr >> 1) + (pr & 1) * 2 + h;
                int dst = dsts[j];
                float M0 = (h ? m0.y : m0.x) * is96;
                float M1 = (h ? m1.y : m1.x) * is96;
                float M2 = (h ? m2.y : m2.x) * is96;
                gate[j] = sigmoidf_(M2) * 0.25f;
                redv2(&g_ags[dst * 64 + lane * 2],
                      siluf_(M0) * 0.25f, siluf_(M1) * 0.25f);
            }
        }
    }

    // ---- phase 2b: vector (mv) matvecs; 16 u64 accumulators live ----
    {
        u64 aB[4], aCx[4], aCy[4], aCz[4];
        #pragma unroll
        for (int p = 0; p < 4; p++) { aB[p] = aCx[p] = aCy[p] = aCz[p] = 0ULL; }

        #pragma unroll 4
        for (int u = 0; u < 64; u++) {
            u64 W = pk2(W2v[u * 32 + lane]);
            #pragma unroll
            for (int q = 0; q < 2; q++) {
                ulonglong2 b = B2[q * 64 + u];
                ff2(aB[2*q], b.x, W); ff2(aB[2*q+1], b.y, W);
            }
        }
        #pragma unroll 4
        for (int u = 0; u < 32; u++) {
            u64 W = pk2(W2v[(64 + u) * 32 + lane]);
            #pragma unroll
            for (int q = 0; q < 2; q++) {
                ulonglong2 cx = C2[q * 96 +      u];
                ulonglong2 cy = C2[q * 96 + 32 + u];
                ulonglong2 cz = C2[q * 96 + 64 + u];
                ff2(aCx[2*q], cx.x, W); ff2(aCx[2*q+1], cx.y, W);
                ff2(aCy[2*q], cy.x, W); ff2(aCy[2*q+1], cy.y, W);
                ff2(aCz[2*q], cz.x, W); ff2(aCz[2*q+1], cz.y, W);
            }
        }

        // ---- phase 3b: paired vector-aggregate scatter ----
        #pragma unroll
        for (int pr = 0; pr < 4; pr++) {
            float2 t1 = up2(aB[pr]);
            float2 cx = up2(aCx[pr]), cy = up2(aCy[pr]), cz = up2(aCz[pr]);
            #pragma unroll
            for (int h = 0; h < 2; h++) {
                int j = 4 * (pr >> 1) + (pr & 1) * 2 + h;
                int e = e0 + j;
                int dst = dsts[j];
                float4 yv = ldcs4((const float4*)ea + e);
                float T1 = (h ? t1.y : t1.x) * is96;
                float Cx = (h ? cx.y : cx.x) * is96;
                float Cy = (h ? cy.y : cy.x) * is96;
                float Cz = (h ? cz.y : cz.x) * is96;
                float g = gate[j];
                float* vp = &g_agv[dst * 128 + lane * 4];
                redv2(vp, (T1 * yv.y + Cx) * g, (T1 * yv.z + Cy) * g);
                redf(vp + 2, (T1 * yv.w + Cz) * g);
            }
        }
    }
}

// ---------------------------------------------------------------------------
// Kernel 3: node post. 8 nodes/block, 192 threads; [k][p] pair layout; ts/tv
// halves run concurrently; f32x2 node-pair packing. Paired aggregate layouts.
// ---------------------------------------------------------------------------
__global__ void __launch_bounds__(192, 2) k_node_post(
    const float* __restrict__ feats,
    const float* __restrict__ attrs,
    const float* __restrict__ Us,   // (64,16)
    const float* __restrict__ Uv,   // (32,16)
    const float* __restrict__ W3s,  // (64,96)
    const float* __restrict__ W3v,  // (32,32)
    const float* __restrict__ SCs,  // (64,16,96)
    const float* __restrict__ SCv,  // (32,16,32)
    float* __restrict__ out)
{
    extern __shared__ float sm[];
    float* cS2    = sm;          // 8192:  [k*8 + p*2 + h]
    float* cV2    = sm + 8192;   // 12288: [(iv*512+k)*8 + p*2 + h]
    float* us2    = sm + 20480;  // 512
    float* uv2    = sm + 20992;  // 768
    float* attr_s = sm + 21760;  // 128
    float* sS     = sm + 21888;  // 512
    float* sV     = sm + 22400;  // 768
    float* gate_s = sm + 23168;  // 256

    int tid = threadIdx.x;
    int nbase = blockIdx.x * 8;

    for (int i = tid; i < 8 * 160; i += 192) {
        int t = i / 160, c = i % 160;
        float v = feats[(nbase + t) * 160 + c];
        if (c < 64) sS[t * 64 + c] = v; else sV[t * 96 + (c - 64)] = v;
    }
    for (int i = tid; i < 128; i += 192) attr_s[i] = attrs[nbase * 16 + i];
    __syncthreads();

    for (int i = tid; i < 8192; i += 192) {
        int h = i & 1, p = (i >> 1) & 3, k = i >> 3;
        int t = 2 * p + h, u = k >> 4, v = k & 15;
        cS2[i] = sS[t * 64 + u] * attr_s[t * 16 + v];
    }
    for (int i = tid; i < 12288; i += 192) {
        int h = i & 1, p = (i >> 1) & 3, kk = i >> 3;
        int iv = kk >> 9, k = kk & 511;
        int t = 2 * p + h, u = k >> 4, v = k & 15;
        cV2[i] = sV[t * 96 + u * 3 + iv] * attr_s[t * 16 + v];
    }
    for (int i = tid; i < 512; i += 192) {
        int h = i & 1, p = (i >> 1) & 3, u = i >> 3;
        int t = 2 * p + h;
        float d = 0.f;
        #pragma unroll
        for (int v = 0; v < 16; v++) d += attr_s[t * 16 + v] * Us[u * 16 + v];
        us2[i] = g_ags[(nbase + t) * 64 + ((u & 31) * 2) + (u >> 5)] * d * 0.25f;
    }
    for (int i = tid; i < 768; i += 192) {
        int h = i & 1, p = (i >> 1) & 3, idx = i >> 3;
        int iv = idx >> 5, u = idx & 31;
        int t = 2 * p + h;
        float d = 0.f;
        #pragma unroll
        for (int v = 0; v < 16; v++) d += attr_s[t * 16 + v] * Uv[u * 16 + v];
        uv2[i] = g_agv[(nbase + t) * 128 + u * 4 + iv] * d * 0.25f;
    }
    __syncthreads();

    int half = tid / 96;
    int r    = tid % 96;

    if (half == 0) {
        int w = r;
        u64 a1[4] = {0,0,0,0}, a2[4] = {0,0,0,0};
        const ulonglong2* us4 = (const ulonglong2*)us2;
        const ulonglong2* cs4 = (const ulonglong2*)cS2;
        #pragma unroll 8
        for (int u = 0; u < 64; u++) {
            u64 W = pk2(W3s[u * 96 + w]);
            ulonglong2 x0 = us4[u * 2 + 0], x1 = us4[u * 2 + 1];
            ff2(a1[0], x0.x, W); ff2(a1[1], x0.y, W);
            ff2(a1[2], x1.x, W); ff2(a1[3], x1.y, W);
        }
        #pragma unroll 8
        for (int k = 0; k < 1024; k++) {
            u64 W = pk2(SCs[k * 96 + w]);
            ulonglong2 x0 = cs4[k * 2 + 0], x1 = cs4[k * 2 + 1];
            ff2(a2[0], x0.x, W); ff2(a2[1], x0.y, W);
            ff2(a2[2], x1.x, W); ff2(a2[3], x1.y, W);
        }
        float ts[8];
        #pragma unroll
        for (int p = 0; p < 4; p++) {
            float2 x1 = up2(a1[p]), x2 = up2(a2[p]);
            ts[2 * p]     = x1.x * 0.125f + x2.x * 0.03125f;
            ts[2 * p + 1] = x1.y * 0.125f + x2.y * 0.03125f;
        }
        if (w < 64) {
            #pragma unroll
            for (int t = 0; t < 8; t++)
                out[(nbase + t) * 160 + w] = siluf_(ts[t]);
        } else {
            #pragma unroll
            for (int t = 0; t < 8; t++)
                gate_s[t * 32 + (w - 64)] = sigmoidf_(ts[t]);
        }
        __syncthreads();
    } else {
        int wv = r & 31, iv = r >> 5;
        u64 b1[4] = {0,0,0,0}, b2[4] = {0,0,0,0};
        const ulonglong2* uv4 = (const ulonglong2*)uv2;
        const ulonglong2* cv4 = (const ulonglong2*)cV2;
        #pragma unroll 8
        for (int u = 0; u < 32; u++) {
            u64 W = pk2(W3v[u * 32 + wv]);
            ulonglong2 x0 = uv4[(iv * 32 + u) * 2 + 0];
            ulonglong2 x1 = uv4[(iv * 32 + u) * 2 + 1];
            ff2(b1[0], x0.x, W); ff2(b1[1], x0.y, W);
            ff2(b1[2], x1.x, W); ff2(b1[3], x1.y, W);
        }
        #pragma unroll 8
        for (int k = 0; k < 512; k++) {
            u64 W = pk2(SCv[k * 32 + wv]);
            ulonglong2 x0 = cv4[(iv * 512 + k) * 2 + 0];
            ulonglong2 x1 = cv4[(iv * 512 + k) * 2 + 1];
            ff2(b2[0], x0.x, W); ff2(b2[1], x0.y, W);
            ff2(b2[2], x1.x, W); ff2(b2[3], x1.y, W);
        }
        __syncthreads();

        const float isv  = 0.17677669529663687f;  // 1/sqrt(32)
        const float isvn = 0.044194173824159220f; // 1/sqrt(512)
        #pragma unroll
        for (int p = 0; p < 4; p++) {
            float2 x1 = up2(b1[p]), x2 = up2(b2[p]);
            float tv0 = x1.x * isv + x2.x * isvn;
            float tv1 = x1.y * isv + x2.y * isvn;
            out[(nbase + 2 * p)     * 160 + 64 + wv * 3 + iv] = tv0 * gate_s[(2 * p)     * 32 + wv];
            out[(nbase + 2 * p + 1) * 160 + 64 + wv * 3 + iv] = tv1 * gate_s[(2 * p + 1) * 32 + wv];
        }
    }
}

// ---------------------------------------------------------------------------
extern "C" void kernel_launch(void* const* d_in, const int* in_sizes, int n_in,
                              void* d_out, int out_size)
{
    const float* node_feats = (const float*)d_in[0];
    const float* node_attrs = (const float*)d_in[1];
    const float* edge_attrs = (const float*)d_in[2];
    const float* edge_emb   = (const float*)d_in[3];
    const float* W1s        = (const float*)d_in[4];
    const float* W1v        = (const float*)d_in[5];
    const float* mw0        = (const float*)d_in[6];
    const float* mw1        = (const float*)d_in[7];
    const float* W2s        = (const float*)d_in[8];
    const float* W2v        = (const float*)d_in[9];
    const float* Us         = (const float*)d_in[10];
    const float* Uv         = (const float*)d_in[11];
    const float* W3s        = (const float*)d_in[12];
    const float* W3v        = (const float*)d_in[13];
    const float* SCs        = (const float*)d_in[14];
    const float* SCv        = (const float*)d_in[15];
    const int*   ei         = (const int*)  d_in[16];
    float* out = (float*)d_out;

    k_node_pre<<<6250, 256>>>(node_feats, W1s, W1v);

    // 25000 blocks * 32 edges = 800000 exactly
    k_mlp<<<25000, 256>>>(edge_emb, mw0, mw1);

    // 25000 blocks * 4 warps * 8 edges = 800000 exactly
    k_edge<<<25000, 128>>>(edge_attrs, W2s, W2v, ei);

    cudaFuncSetAttribute(k_node_post, cudaFuncAttributeMaxDynamicSharedMemorySize, 94208);
    k_node_post<<<6250, 192, 93696>>>(node_feats, node_attrs, Us, Uv, W3s, W3v,
                                      SCs, SCv, out);
}